// round 11
// baseline (speedup 1.0000x reference)
#include <cuda_runtime.h>
#include <cuda_bf16.h>
#include <math.h>
#include <stdint.h>

#define BATCH  32768
#define EMB    256
#define ADIM   64
#define NHEADS 2
#define KNEI   16

// ---------------- scratch (device globals; no allocation allowed) ----------------
__device__ __nv_bfloat16 g_ch [BATCH * EMB];     // center gathered, bf16 hi
__device__ __nv_bfloat16 g_cl [BATCH * EMB];     // center gathered, bf16 lo
__device__ float         g_qk [BATCH * 512];     // qk fp32 (compacted)
__device__ __nv_bfloat16 g_cxh[BATCH * 512];     // ctx hi
__device__ __nv_bfloat16 g_cxl[BATCH * 512];     // ctx lo
__device__ __nv_bfloat16 g_wqh[128 * 256], g_wql[128 * 256];
__device__ __nv_bfloat16 g_wkh[NHEADS * 256 * 64], g_wkl[NHEADS * 256 * 64];  // WkT [h][d][a]
__device__ __nv_bfloat16 g_woh[256 * 512], g_wol[256 * 512];
__device__ int g_valid[BATCH];
__device__ int g_perm [BATCH];    // [0,nv): valid rows, [nv,BATCH): invalid rows
__device__ int g_nvalid;

// ---------------- helpers ----------------
__device__ __forceinline__ uint32_t smem_u32(const void* p) {
    uint32_t a;
    asm("{ .reg .u64 t; cvta.to.shared.u64 t, %1; cvt.u32.u64 %0, t; }" : "=r"(a) : "l"(p));
    return a;
}

#define LDSM4(r0, r1, r2, r3, addr) \
    asm volatile("ldmatrix.sync.aligned.m8n8.x4.shared.b16 {%0,%1,%2,%3}, [%4];" \
                 : "=r"(r0), "=r"(r1), "=r"(r2), "=r"(r3) : "r"(addr))

#define MMA16816(d, a, b0, b1) \
    asm volatile("mma.sync.aligned.m16n8k16.row.col.f32.bf16.bf16.f32 " \
                 "{%0,%1,%2,%3}, {%4,%5,%6,%7}, {%8,%9}, {%0,%1,%2,%3};" \
                 : "+f"((d)[0]), "+f"((d)[1]), "+f"((d)[2]), "+f"((d)[3]) \
                 : "r"((a)[0]), "r"((a)[1]), "r"((a)[2]), "r"((a)[3]), \
                   "r"(b0), "r"(b1))

#define CP16(dst, src) \
    asm volatile("cp.async.cg.shared.global [%0], [%1], 16;" :: "r"(dst), "l"(src) : "memory")
#define CPCOMMIT() asm volatile("cp.async.commit_group;" ::: "memory")
#define CPWAIT1()  asm volatile("cp.async.wait_group 1;" ::: "memory")
#define CPWAIT0()  asm volatile("cp.async.wait_group 0;" ::: "memory")

__device__ __forceinline__ void split1(float v, __nv_bfloat16* hi, __nv_bfloat16* lo) {
    __nv_bfloat16 h = __float2bfloat16(v);
    *hi = h;
    *lo = __float2bfloat16(v - __bfloat162float(h));
}

// ---------------- mask detect + expand + ordered two-sided compaction ----------------
__global__ void mask_compact(const void* __restrict__ mptr) {
    __shared__ int s[1024];
    __shared__ int flag;
    const int t = threadIdx.x;

    if (t == 0) flag = 0;
    __syncthreads();
    const unsigned int* mw = (const unsigned int*)mptr;
    int found = 0;
    for (int i = t; i < 2048; i += 1024)
        if (mw[i] > 1u) found = 1;
    if (found) flag = 1;
    __syncthreads();
    const int byteMode = flag;

    const int base = t * 32;
    int v[32];
    int c = 0;
    #pragma unroll
    for (int i = 0; i < 32; i++) {
        int b = base + i;
        int val = byteMode ? (((const unsigned char*)mptr)[b] != 0)
                           : (((const int*)mptr)[b] != 0);
        v[i] = val;
        g_valid[b] = val;
        c += val;
    }
    s[t] = c;
    __syncthreads();
    for (int off = 1; off < 1024; off <<= 1) {
        int x = (t >= off) ? s[t - off] : 0;
        __syncthreads();
        s[t] += x;
        __syncthreads();
    }
    const int total = s[1023];
    int o  = s[t] - c;
    int oi = total + (base - o);
    #pragma unroll
    for (int i = 0; i < 32; i++) {
        int b = base + i;
        if (v[i]) g_perm[o++]  = b;
        else      g_perm[oi++] = b;
    }
    if (t == 0) g_nvalid = total;
}

// ---------------- weight prep: split Wq, transpose+split Wk, split Wout ----------------
__global__ void prep_weights(const float* __restrict__ Wq,
                             const float* __restrict__ Wk,
                             const float* __restrict__ Wout) {
    int idx = blockIdx.x * blockDim.x + threadIdx.x;   // 0 .. 196607
    if (idx < 32768) {
        split1(Wq[idx], g_wqh + idx, g_wql + idx);
    } else if (idx < 65536) {
        int j = idx - 32768;
        int h = j / (ADIM * EMB);
        int r = j - h * (ADIM * EMB);
        int a = r / EMB;
        int d = r - a * EMB;
        int o = h * EMB * ADIM + d * ADIM + a;
        split1(Wk[j], g_wkh + o, g_wkl + o);
    } else {
        int j = idx - 65536;
        split1(Wout[j], g_woh + j, g_wol + j);
    }
}

__global__ void gather_split_center(const float* __restrict__ center) {
    int i = blockIdx.x * blockDim.x + threadIdx.x;   // over BATCH*EMB
    int row = i >> 8, d = i & 255;
    if (row >= g_nvalid) return;
    float v = center[(size_t)g_perm[row] * EMB + d];
    split1(v, g_ch + i, g_cl + i);
}

// ======================= GEMM tiling constants (BM=64, BN=128) =======================
// 8 warps as 2 (m) x 4 (n); warp tile 32x32.
#define PADB   80
#define MATB_A (64 * PADB)                 // 5120  bytes (A hi or lo)
#define MATB_B (128 * PADB)                // 10240 bytes (B hi or lo)
#define STGB   (2 * MATB_A + 2 * MATB_B)   // 30720 bytes per stage
#define SMEM_TOT (2 * STGB)                // 61440 (out-GEMM)

// fused q->qk kernel smem layout
#define QSTRIDE 272                        // 128 cols * 2B + 16 pad
#define SQ_HI   0
#define SQ_LO   (64 * QSTRIDE)             // 17408
#define SB_OFF  (2 * 64 * QSTRIDE)         // 34816
#define SB_STR  144                        // 64 cols * 2B + 16 pad
#define SB_MATB (128 * SB_STR)             // 18432
#define FUSED_SMEM (SB_OFF + 2 * SB_MATB)  // 71680

// ---------------- fused q -> qk kernel (BM=64) ----------------
__global__ __launch_bounds__(256, 2) void q_qk_fused()
{
    extern __shared__ __align__(16) char dynsm[];

    const int nvalid = g_nvalid;
    const int m0 = blockIdx.x * 64;
    if (m0 >= nvalid) return;

    const int t    = threadIdx.x;
    const int wid  = t >> 5;
    const int lane = t & 31;
    const int wm   = wid >> 2;          // 0..1 -> m offset wm*32
    const int wn   = wid & 3;           // 0..3 -> n offset wn*32

    const uint32_t sbase = smem_u32(dynsm);

    float c[2][4][4];
    #pragma unroll
    for (int mi = 0; mi < 2; mi++)
        #pragma unroll
        for (int t4 = 0; t4 < 4; t4++)
            #pragma unroll
            for (int r = 0; r < 4; r++) c[mi][t4][r] = 0.f;

    const int la = lane & 15, ga = lane >> 4;
    const int lb = lane & 7,  gb = lane >> 3;

    // ---------- phase 1: q = center @ Wq^T (K=256, BK=32, double buffered) ----------
    {
        const uint32_t aoff = (uint32_t)((wm * 32 + la) * PADB + ga * 16);
        const uint32_t boff = (uint32_t)((wn * 32 + lb + (gb >> 1) * 8) * PADB + (gb & 1) * 16);

        auto load_stage = [&](int s, int buf) {
            const int kb = s * 32;
            const uint32_t dstb = sbase + (uint32_t)buf * STGB;
            #pragma unroll
            for (int i = 0; i < 6; i++) {          // 1536 chunks, 6/thread
                int idx = i * 256 + t;
                const __nv_bfloat16* src;
                uint32_t dst;
                if (idx < 512) {                    // A hi/lo: 64 rows x 4 chunks
                    int mat = idx >> 8;             // 0 hi, 1 lo
                    int rem = idx & 255;
                    int row = rem >> 2, c4 = rem & 3;
                    src = (mat ? g_cl : g_ch) + (size_t)(m0 + row) * EMB + kb + c4 * 8;
                    dst = dstb + (uint32_t)mat * MATB_A + (uint32_t)(row * PADB + c4 * 16);
                } else {                            // B hi/lo: 128 rows x 4 chunks
                    int j = idx - 512;
                    int mat = j >> 9;
                    int rem = j & 511;
                    int row = rem >> 2, c4 = rem & 3;
                    src = (mat ? g_wql : g_wqh) + (size_t)row * EMB + kb + c4 * 8;
                    dst = dstb + 2 * MATB_A + (uint32_t)mat * MATB_B
                              + (uint32_t)(row * PADB + c4 * 16);
                }
                CP16(dst, src);
            }
            CPCOMMIT();
        };

        load_stage(0, 0);
        const int nStages = 8;
        for (int s = 0; s < nStages; s++) {
            const int buf = s & 1;
            const bool more = (s + 1 < nStages);
            if (more) load_stage(s + 1, buf ^ 1);
            if (more) CPWAIT1(); else CPWAIT0();
            __syncthreads();

            const uint32_t bS = sbase + (uint32_t)buf * STGB;
            const uint32_t bAhi = bS, bAlo = bS + MATB_A;
            const uint32_t bBhi = bS + 2 * MATB_A, bBlo = bS + 2 * MATB_A + MATB_B;

            #pragma unroll
            for (int kk = 0; kk < 2; kk++) {
                const uint32_t kby = kk * 32;
                uint32_t ah[2][4], al[2][4];
                #pragma unroll
                for (int mi = 0; mi < 2; mi++) {
                    uint32_t adr = (uint32_t)((wm * 32 + mi * 16 + la) * PADB + ga * 16) + kby;
                    LDSM4(ah[mi][0], ah[mi][1], ah[mi][2], ah[mi][3], bAhi + adr);
                    LDSM4(al[mi][0], al[mi][1], al[mi][2], al[mi][3], bAlo + adr);
                }
                uint32_t bh[2][4], bl[2][4];
                #pragma unroll
                for (int nj = 0; nj < 2; nj++) {
                    uint32_t adr = (uint32_t)((wn * 32 + nj * 16 + lb + (gb >> 1) * 8) * PADB
                                              + (gb & 1) * 16) + kby;
                    LDSM4(bh[nj][0], bh[nj][1], bh[nj][2], bh[nj][3], bBhi + adr);
                    LDSM4(bl[nj][0], bl[nj][1], bl[nj][2], bl[nj][3], bBlo + adr);
                }
                #pragma unroll
                for (int mi = 0; mi < 2; mi++)
                    #pragma unroll
                    for (int t4 = 0; t4 < 4; t4++) {
                        const int nj = t4 >> 1, sel = (t4 & 1) * 2;
                        MMA16816(c[mi][t4], ah[mi], bh[nj][sel], bh[nj][sel + 1]);
                        MMA16816(c[mi][t4], al[mi], bh[nj][sel], bh[nj][sel + 1]);
                        MMA16816(c[mi][t4], ah[mi], bl[nj][sel], bl[nj][sel + 1]);
                    }
            }
            __syncthreads();
        }
    }

    // ---------- split q accums into smem ----------
    const int rit  = lane >> 2;
    const int colp = (lane & 3) * 2;
    #pragma unroll
    for (int mi = 0; mi < 2; mi++) {
        #pragma unroll
        for (int half = 0; half < 2; half++) {
            const int row = wm * 32 + mi * 16 + half * 8 + rit;
            #pragma unroll
            for (int t4 = 0; t4 < 4; t4++) {
                const int col = wn * 32 + t4 * 8 + colp;
                float v0 = c[mi][t4][half * 2 + 0];
                float v1 = c[mi][t4][half * 2 + 1];
                __nv_bfloat16 h0 = __float2bfloat16(v0);
                __nv_bfloat16 h1 = __float2bfloat16(v1);
                __nv_bfloat16 l0 = __float2bfloat16(v0 - __bfloat162float(h0));
                __nv_bfloat16 l1 = __float2bfloat16(v1 - __bfloat162float(h1));
                const uint32_t off = (uint32_t)(row * QSTRIDE + col * 2);
                *reinterpret_cast<__nv_bfloat162*>(dynsm + SQ_HI + off) = __nv_bfloat162(h0, h1);
                *reinterpret_cast<__nv_bfloat162*>(dynsm + SQ_LO + off) = __nv_bfloat162(l0, l1);
            }
        }
    }
    __syncthreads();

    // ---------- phase 2: qk[:, nt*128 .. ] = q @ WkT ----------
    const uint32_t sqhi = sbase + SQ_HI;
    const uint32_t sqlo = sbase + SQ_LO;
    const uint32_t sbhi = sbase + SB_OFF;
    const uint32_t sblo = sbase + SB_OFF + SB_MATB;

    for (int nt = 0; nt < 4; nt++) {
        const int h   = nt >> 1;
        const int sub = nt & 1;
        const size_t brow0 = (size_t)(h * EMB + sub * 128) * ADIM;

        // load WkT tile (128 d-rows x 64 a-cols, hi+lo): 2048 chunks, 8/thread
        #pragma unroll
        for (int i = 0; i < 8; i++) {
            int idx = i * 256 + t;
            int mat = idx >> 10;
            int rem = idx & 1023;
            int row = rem >> 3, c8 = rem & 7;
            const __nv_bfloat16* src = (mat ? g_wkl : g_wkh) + brow0 + (size_t)row * ADIM + c8 * 8;
            uint32_t dst = (mat ? sblo : sbhi) + (uint32_t)(row * SB_STR + c8 * 16);
            CP16(dst, src);
        }
        CPCOMMIT(); CPWAIT0();
        __syncthreads();

        #pragma unroll
        for (int mi = 0; mi < 2; mi++)
            #pragma unroll
            for (int t4 = 0; t4 < 4; t4++)
                #pragma unroll
                for (int r = 0; r < 4; r++) c[mi][t4][r] = 0.f;

        #pragma unroll
        for (int kk = 0; kk < 4; kk++) {
            const uint32_t kby = kk * 32;
            uint32_t ah[2][4], al[2][4];
            #pragma unroll
            for (int mi = 0; mi < 2; mi++) {
                uint32_t adr = (uint32_t)((wm * 32 + mi * 16 + la) * QSTRIDE + ga * 16 + h * 128) + kby;
                LDSM4(ah[mi][0], ah[mi][1], ah[mi][2], ah[mi][3], sqhi + adr);
                LDSM4(al[mi][0], al[mi][1], al[mi][2], al[mi][3], sqlo + adr);
            }
            uint32_t bh[2][4], bl[2][4];
            #pragma unroll
            for (int nj = 0; nj < 2; nj++) {
                uint32_t adr = (uint32_t)((wn * 32 + nj * 16 + lb + (gb >> 1) * 8) * SB_STR
                                          + (gb & 1) * 16) + kby;
                LDSM4(bh[nj][0], bh[nj][1], bh[nj][2], bh[nj][3], sbhi + adr);
                LDSM4(bl[nj][0], bl[nj][1], bl[nj][2], bl[nj][3], sblo + adr);
            }
            #pragma unroll
            for (int mi = 0; mi < 2; mi++)
                #pragma unroll
                for (int t4 = 0; t4 < 4; t4++) {
                    const int nj = t4 >> 1, sel = (t4 & 1) * 2;
                    MMA16816(c[mi][t4], ah[mi], bh[nj][sel], bh[nj][sel + 1]);
                    MMA16816(c[mi][t4], al[mi], bh[nj][sel], bh[nj][sel + 1]);
                    MMA16816(c[mi][t4], ah[mi], bl[nj][sel], bl[nj][sel + 1]);
                }
        }

        // epilogue: write qk fp32
        #pragma unroll
        for (int mi = 0; mi < 2; mi++) {
            #pragma unroll
            for (int half = 0; half < 2; half++) {
                const int gm = m0 + wm * 32 + mi * 16 + half * 8 + rit;
                #pragma unroll
                for (int t4 = 0; t4 < 4; t4++) {
                    const int col = nt * 128 + wn * 32 + t4 * 8 + colp;
                    *reinterpret_cast<float2*>(g_qk + (size_t)gm * 512 + col) =
                        make_float2(c[mi][t4][half * 2 + 0], c[mi][t4][half * 2 + 1]);
                }
            }
        }
        __syncthreads();
    }
}

// ---------------- generic bf16x3 HMMA GEMM (out-GEMM), BM=64 ----------------
__global__ __launch_bounds__(256, 2) void gemm_mma(
    const __nv_bfloat16* __restrict__ Ahi, const __nv_bfloat16* __restrict__ Alo,
    int lda,
    const __nv_bfloat16* __restrict__ Bhi, const __nv_bfloat16* __restrict__ Blo,
    int ldb, int Kdim,
    float* __restrict__ Cf, int ldcf,
    const float* __restrict__ bias,
    const int* __restrict__ Cperm)
{
    extern __shared__ __align__(16) char dynsm[];

    const int nvalid = g_nvalid;
    const int m0 = blockIdx.y * 64;
    if (m0 >= nvalid) return;
    const int n0 = blockIdx.x * 128;

    const int t    = threadIdx.x;
    const int wid  = t >> 5;
    const int lane = t & 31;
    const int wm   = wid >> 2;
    const int wn   = wid & 3;

    const uint32_t sbase = smem_u32(dynsm);

    float c[2][4][4];
    #pragma unroll
    for (int mi = 0; mi < 2; mi++)
        #pragma unroll
        for (int t4 = 0; t4 < 4; t4++)
            #pragma unroll
            for (int r = 0; r < 4; r++) c[mi][t4][r] = 0.f;

    const int la = lane & 15, ga = lane >> 4;
    const int lb = lane & 7,  gb = lane >> 3;

    const int nStages = Kdim >> 5;

    auto load_stage = [&](int s, int buf) {
        const int kb = s * 32;
        const uint32_t dstb = sbase + (uint32_t)buf * STGB;
        #pragma unroll
        for (int i = 0; i < 6; i++) {
            int idx = i * 256 + t;
            const __nv_bfloat16* src;
            uint32_t dst;
            if (idx < 512) {
                int mat = idx >> 8;
                int rem = idx & 255;
                int row = rem >> 2, c4 = rem & 3;
                src = (mat ? Alo : Ahi) + (size_t)(m0 + row) * lda + kb + c4 * 8;
                dst = dstb + (uint32_t)mat * MATB_A + (uint32_t)(row * PADB + c4 * 16);
            } else {
                int j = idx - 512;
                int mat = j >> 9;
                int rem = j & 511;
                int row = rem >> 2, c4 = rem & 3;
                src = (mat ? Blo : Bhi) + (size_t)(n0 + row) * ldb + kb + c4 * 8;
                dst = dstb + 2 * MATB_A + (uint32_t)mat * MATB_B
                          + (uint32_t)(row * PADB + c4 * 16);
            }
            CP16(dst, src);
        }
        CPCOMMIT();
    };

    load_stage(0, 0);

    for (int s = 0; s < nStages; s++) {
        const int buf = s & 1;
        const bool more = (s + 1 < nStages);
        if (more) load_stage(s + 1, buf ^ 1);
        if (more) CPWAIT1(); else CPWAIT0();
        __syncthreads();

        const uint32_t bS = sbase + (uint32_t)buf * STGB;
        const uint32_t bAhi = bS, bAlo = bS + MATB_A;
        const uint32_t bBhi = bS + 2 * MATB_A, bBlo = bS + 2 * MATB_A + MATB_B;

        #pragma unroll
        for (int kk = 0; kk < 2; kk++) {
            const uint32_t kby = kk * 32;
            uint32_t ah[2][4], al[2][4];
            #pragma unroll
            for (int mi = 0; mi < 2; mi++) {
                uint32_t adr = (uint32_t)((wm * 32 + mi * 16 + la) * PADB + ga * 16) + kby;
                LDSM4(ah[mi][0], ah[mi][1], ah[mi][2], ah[mi][3], bAhi + adr);
                LDSM4(al[mi][0], al[mi][1], al[mi][2], al[mi][3], bAlo + adr);
            }
            uint32_t bh[2][4], bl[2][4];
            #pragma unroll
            for (int nj = 0; nj < 2; nj++) {
                uint32_t adr = (uint32_t)((wn * 32 + nj * 16 + lb + (gb >> 1) * 8) * PADB
                                          + (gb & 1) * 16) + kby;
                LDSM4(bh[nj][0], bh[nj][1], bh[nj][2], bh[nj][3], bBhi + adr);
                LDSM4(bl[nj][0], bl[nj][1], bl[nj][2], bl[nj][3], bBlo + adr);
            }
            #pragma unroll
            for (int mi = 0; mi < 2; mi++)
                #pragma unroll
                for (int t4 = 0; t4 < 4; t4++) {
                    const int nj = t4 >> 1, sel = (t4 & 1) * 2;
                    MMA16816(c[mi][t4], ah[mi], bh[nj][sel], bh[nj][sel + 1]);
                    MMA16816(c[mi][t4], al[mi], bh[nj][sel], bh[nj][sel + 1]);
                    MMA16816(c[mi][t4], ah[mi], bl[nj][sel], bl[nj][sel + 1]);
                }
        }
        __syncthreads();
    }

    const int rit  = lane >> 2;
    const int colp = (lane & 3) * 2;
    #pragma unroll
    for (int mi = 0; mi < 2; mi++) {
        #pragma unroll
        for (int half = 0; half < 2; half++) {
            const int gm = m0 + wm * 32 + mi * 16 + half * 8 + rit;
            if (gm >= nvalid) continue;
            const int crow = Cperm ? Cperm[gm] : gm;
            #pragma unroll
            for (int t4 = 0; t4 < 4; t4++) {
                const int col = n0 + wn * 32 + t4 * 8 + colp;
                float v0 = c[mi][t4][half * 2 + 0];
                float v1 = c[mi][t4][half * 2 + 1];
                if (bias) { v0 += bias[col]; v1 += bias[col + 1]; }
                *reinterpret_cast<float2*>(Cf + (size_t)crow * ldcf + col) =
                    make_float2(v0, v1);
            }
        }
    }
}

// ---------------- fused attention (valid) + passthrough copy (invalid) ----------------
__global__ __launch_bounds__(128) void attn_kernel(
    const float* __restrict__ center,
    const float* __restrict__ neigh,
    const float* __restrict__ wts,
    const float* __restrict__ qk,
    float* __restrict__ out)
{
    const int i = blockIdx.x;
    const int t = threadIdx.x;
    const int b = g_perm[i];

    if (i >= g_nvalid) {
        const float4* src = reinterpret_cast<const float4*>(center + (long)b * EMB);
        float4*       dst = reinterpret_cast<float4*>(out + (long)b * EMB);
        if (t < 64) dst[t] = src[t];
        return;
    }

    __shared__ float sn[KNEI * EMB];
    __shared__ float sq[512];
    __shared__ float sscore[32];
    __shared__ float sattn[32];

    const float4* np = reinterpret_cast<const float4*>(neigh + (long)b * KNEI * EMB);
    float4* snp = reinterpret_cast<float4*>(sn);
    #pragma unroll
    for (int r = 0; r < 8; r++) snp[t + r * 128] = np[t + r * 128];
    reinterpret_cast<float4*>(sq)[t] =
        reinterpret_cast<const float4*>(qk + (long)i * 512)[t];
    __syncthreads();

    {
        const int g = t >> 2, sub = t & 3;
        const int h = g >> 4, j = g & 15;
        const float* qh = sq + h * EMB;
        const float* nj = sn + j * EMB;
        float p = 0.f;
        #pragma unroll 8
        for (int d = sub; d < EMB; d += 4) p += qh[d] * nj[d];
        p += __shfl_xor_sync(0xffffffffu, p, 1);
        p += __shfl_xor_sync(0xffffffffu, p, 2);
        if (sub == 0) sscore[g] = p * 0.125f;
    }
    __syncthreads();

    {
        const int wid = t >> 5, lane = t & 31;
        if (wid < NHEADS && lane < KNEI) {
            float s = sscore[wid * KNEI + lane];
            float m = s;
            #pragma unroll
            for (int o = 8; o > 0; o >>= 1) m = fmaxf(m, __shfl_xor_sync(0xffffu, m, o));
            float e = expf(s - m);
            float se = e;
            #pragma unroll
            for (int o = 8; o > 0; o >>= 1) se += __shfl_xor_sync(0xffffu, se, o);
            float a = (e / se) * wts[b * KNEI + lane];
            float sa = a;
            #pragma unroll
            for (int o = 8; o > 0; o >>= 1) sa += __shfl_xor_sync(0xffffu, sa, o);
            sattn[wid * KNEI + lane] = a / (sa + 1e-8f);
        }
    }
    __syncthreads();

    #pragma unroll
    for (int r = 0; r < 4; r++) {
        const int idx = r * 128 + t;
        const int d = idx & 255, h = idx >> 8;
        float acc = 0.f;
        #pragma unroll
        for (int j = 0; j < KNEI; j++) acc += sattn[h * KNEI + j] * sn[j * EMB + d];
        __nv_bfloat16 hi = __float2bfloat16(acc);
        g_cxh[(size_t)i * 512 + idx] = hi;
        g_cxl[(size_t)i * 512 + idx] = __float2bfloat16(acc - __bfloat162float(hi));
    }
}

// ---------------- launch ----------------
extern "C" void kernel_launch(void* const* d_in, const int* in_sizes, int n_in,
                              void* d_out, int out_size)
{
    const float* center = (const float*)d_in[0];
    const float* neigh  = (const float*)d_in[1];
    const float* wts    = (const float*)d_in[2];
    const void*  mask   = d_in[3];
    const float* Wq     = (const float*)d_in[4];   // [2, 64, 256]
    const float* Wk     = (const float*)d_in[5];   // [2, 64, 256]
    const float* Wout   = (const float*)d_in[6];   // [256, 512]
    const float* bout   = (const float*)d_in[7];
    float* out = (float*)d_out;

    __nv_bfloat16 *cxh, *cxl, *woh, *wol;
    float *gqk;
    int *gperm;
    cudaGetSymbolAddress((void**)&cxh, g_cxh); cudaGetSymbolAddress((void**)&cxl, g_cxl);
    cudaGetSymbolAddress((void**)&woh, g_woh); cudaGetSymbolAddress((void**)&wol, g_wol);
    cudaGetSymbolAddress((void**)&gqk, g_qk);
    cudaGetSymbolAddress((void**)&gperm, g_perm);

    cudaFuncSetAttribute(gemm_mma, cudaFuncAttributeMaxDynamicSharedMemorySize, SMEM_TOT);
    cudaFuncSetAttribute(q_qk_fused, cudaFuncAttributeMaxDynamicSharedMemorySize, FUSED_SMEM);

    mask_compact<<<1, 1024>>>(mask);
    prep_weights<<<196608 / 256, 256>>>(Wq, Wk, Wout);
    gather_split_center<<<(BATCH * EMB) / 256, 256>>>(center);

    // fused q->qk: [Bv,512] in one kernel, q never leaves smem
    q_qk_fused<<<BATCH / 64, 256, FUSED_SMEM>>>();

    // attention on valid rows + passthrough on invalid rows
    attn_kernel<<<BATCH, 128>>>(center, neigh, wts, gqk, out);

    // out = ctx @ Wout^T + b : [Bv,256], K=512 -> fp32 scattered via perm
    {
        dim3 grid(2, BATCH / 64);
        gemm_mma<<<grid, 256, SMEM_TOT>>>(cxh, cxl, 512, woh, wol, 512, 512,
                                          out, EMB, bout, gperm);
    }
}

// round 12
// speedup vs baseline: 1.0195x; 1.0195x over previous
#include <cuda_runtime.h>
#include <cuda_bf16.h>
#include <math.h>
#include <stdint.h>

#define BATCH  32768
#define EMB    256
#define ADIM   64
#define NHEADS 2
#define KNEI   16

// ---------------- scratch (device globals; no allocation allowed) ----------------
__device__ __nv_bfloat16 g_ch [BATCH * EMB];     // center gathered, bf16 hi
__device__ __nv_bfloat16 g_cl [BATCH * EMB];     // center gathered, bf16 lo
__device__ float         g_qk [BATCH * 512];     // qk fp32 (compacted)
__device__ __nv_bfloat16 g_cxh[BATCH * 512];     // ctx hi
__device__ __nv_bfloat16 g_cxl[BATCH * 512];     // ctx lo
__device__ __nv_bfloat16 g_wqh[128 * 256], g_wql[128 * 256];
__device__ __nv_bfloat16 g_wkh[NHEADS * 256 * 64], g_wkl[NHEADS * 256 * 64];  // WkT [h][d][a]
__device__ __nv_bfloat16 g_woh[256 * 512], g_wol[256 * 512];
__device__ int g_valid[BATCH];
__device__ int g_perm [BATCH];    // [0,nv): valid rows, [nv,BATCH): invalid rows
__device__ int g_nvalid;

// ---------------- helpers ----------------
__device__ __forceinline__ uint32_t smem_u32(const void* p) {
    uint32_t a;
    asm("{ .reg .u64 t; cvta.to.shared.u64 t, %1; cvt.u32.u64 %0, t; }" : "=r"(a) : "l"(p));
    return a;
}

#define LDSM4(r0, r1, r2, r3, addr) \
    asm volatile("ldmatrix.sync.aligned.m8n8.x4.shared.b16 {%0,%1,%2,%3}, [%4];" \
                 : "=r"(r0), "=r"(r1), "=r"(r2), "=r"(r3) : "r"(addr))

#define MMA16816(d, a, b0, b1) \
    asm volatile("mma.sync.aligned.m16n8k16.row.col.f32.bf16.bf16.f32 " \
                 "{%0,%1,%2,%3}, {%4,%5,%6,%7}, {%8,%9}, {%0,%1,%2,%3};" \
                 : "+f"((d)[0]), "+f"((d)[1]), "+f"((d)[2]), "+f"((d)[3]) \
                 : "r"((a)[0]), "r"((a)[1]), "r"((a)[2]), "r"((a)[3]), \
                   "r"(b0), "r"(b1))

#define CP16(dst, src) \
    asm volatile("cp.async.cg.shared.global [%0], [%1], 16;" :: "r"(dst), "l"(src) : "memory")
#define CPCOMMIT() asm volatile("cp.async.commit_group;" ::: "memory")
#define CPWAIT1()  asm volatile("cp.async.wait_group 1;" ::: "memory")
#define CPWAIT0()  asm volatile("cp.async.wait_group 0;" ::: "memory")

__device__ __forceinline__ void split1(float v, __nv_bfloat16* hi, __nv_bfloat16* lo) {
    __nv_bfloat16 h = __float2bfloat16(v);
    *hi = h;
    *lo = __float2bfloat16(v - __bfloat162float(h));
}

// ---------------- mask detect + expand + ordered two-sided compaction ----------------
__global__ void mask_compact(const void* __restrict__ mptr) {
    __shared__ int s[1024];
    __shared__ int flag;
    const int t = threadIdx.x;

    if (t == 0) flag = 0;
    __syncthreads();
    const unsigned int* mw = (const unsigned int*)mptr;
    int found = 0;
    for (int i = t; i < 2048; i += 1024)
        if (mw[i] > 1u) found = 1;
    if (found) flag = 1;
    __syncthreads();
    const int byteMode = flag;

    const int base = t * 32;
    int v[32];
    int c = 0;
    #pragma unroll
    for (int i = 0; i < 32; i++) {
        int b = base + i;
        int val = byteMode ? (((const unsigned char*)mptr)[b] != 0)
                           : (((const int*)mptr)[b] != 0);
        v[i] = val;
        g_valid[b] = val;
        c += val;
    }
    s[t] = c;
    __syncthreads();
    for (int off = 1; off < 1024; off <<= 1) {
        int x = (t >= off) ? s[t - off] : 0;
        __syncthreads();
        s[t] += x;
        __syncthreads();
    }
    const int total = s[1023];
    int o  = s[t] - c;
    int oi = total + (base - o);
    #pragma unroll
    for (int i = 0; i < 32; i++) {
        int b = base + i;
        if (v[i]) g_perm[o++]  = b;
        else      g_perm[oi++] = b;
    }
    if (t == 0) g_nvalid = total;
}

// ---------------- weight prep: split Wq, transpose+split Wk, split Wout ----------------
__global__ void prep_weights(const float* __restrict__ Wq,
                             const float* __restrict__ Wk,
                             const float* __restrict__ Wout) {
    int idx = blockIdx.x * blockDim.x + threadIdx.x;   // 0 .. 196607
    if (idx < 32768) {
        split1(Wq[idx], g_wqh + idx, g_wql + idx);
    } else if (idx < 65536) {
        int j = idx - 32768;
        int h = j / (ADIM * EMB);
        int r = j - h * (ADIM * EMB);
        int a = r / EMB;
        int d = r - a * EMB;
        int o = h * EMB * ADIM + d * ADIM + a;
        split1(Wk[j], g_wkh + o, g_wkl + o);
    } else {
        int j = idx - 65536;
        split1(Wout[j], g_woh + j, g_wol + j);
    }
}

__global__ void gather_split_center(const float* __restrict__ center) {
    int i = blockIdx.x * blockDim.x + threadIdx.x;   // over BATCH*EMB
    int row = i >> 8, d = i & 255;
    if (row >= g_nvalid) return;
    float v = center[(size_t)g_perm[row] * EMB + d];
    split1(v, g_ch + i, g_cl + i);
}

// ======================= q_qk fused kernel constants (BM=64, BN=128) =======================
// 8 warps as 2 (m) x 4 (n); warp tile 32x32.
#define PADB   80
#define MATB_A (64 * PADB)                 // 5120  bytes (A hi or lo)
#define MATB_B (128 * PADB)                // 10240 bytes (B hi or lo)
#define STGB   (2 * MATB_A + 2 * MATB_B)   // 30720 bytes per stage

// fused q->qk kernel smem layout
#define QSTRIDE 272                        // 128 cols * 2B + 16 pad
#define SQ_HI   0
#define SQ_LO   (64 * QSTRIDE)             // 17408
#define SB_OFF  (2 * 64 * QSTRIDE)         // 34816
#define SB_STR  144                        // 64 cols * 2B + 16 pad
#define SB_MATB (128 * SB_STR)             // 18432
#define FUSED_SMEM (SB_OFF + 2 * SB_MATB)  // 71680

// ======================= out-GEMM constants (BM=128, BN=128) =======================
#define OG_MATB (128 * PADB)               // 10240 bytes per matrix
#define OG_STGB (4 * OG_MATB)              // 40960 bytes per stage
#define OG_SMEM (2 * OG_STGB)              // 81920 -> 2 CTAs/SM

// ---------------- fused q -> qk kernel (BM=64) ----------------
__global__ __launch_bounds__(256, 2) void q_qk_fused()
{
    extern __shared__ __align__(16) char dynsm[];

    const int nvalid = g_nvalid;
    const int m0 = blockIdx.x * 64;
    if (m0 >= nvalid) return;

    const int t    = threadIdx.x;
    const int wid  = t >> 5;
    const int lane = t & 31;
    const int wm   = wid >> 2;          // 0..1 -> m offset wm*32
    const int wn   = wid & 3;           // 0..3 -> n offset wn*32

    const uint32_t sbase = smem_u32(dynsm);

    float c[2][4][4];
    #pragma unroll
    for (int mi = 0; mi < 2; mi++)
        #pragma unroll
        for (int t4 = 0; t4 < 4; t4++)
            #pragma unroll
            for (int r = 0; r < 4; r++) c[mi][t4][r] = 0.f;

    const int la = lane & 15, ga = lane >> 4;
    const int lb = lane & 7,  gb = lane >> 3;

    // ---------- phase 1: q = center @ Wq^T (K=256, BK=32, double buffered) ----------
    {
        auto load_stage = [&](int s, int buf) {
            const int kb = s * 32;
            const uint32_t dstb = sbase + (uint32_t)buf * STGB;
            #pragma unroll
            for (int i = 0; i < 6; i++) {          // 1536 chunks, 6/thread
                int idx = i * 256 + t;
                const __nv_bfloat16* src;
                uint32_t dst;
                if (idx < 512) {                    // A hi/lo: 64 rows x 4 chunks
                    int mat = idx >> 8;             // 0 hi, 1 lo
                    int rem = idx & 255;
                    int row = rem >> 2, c4 = rem & 3;
                    src = (mat ? g_cl : g_ch) + (size_t)(m0 + row) * EMB + kb + c4 * 8;
                    dst = dstb + (uint32_t)mat * MATB_A + (uint32_t)(row * PADB + c4 * 16);
                } else {                            // B hi/lo: 128 rows x 4 chunks
                    int j = idx - 512;
                    int mat = j >> 9;
                    int rem = j & 511;
                    int row = rem >> 2, c4 = rem & 3;
                    src = (mat ? g_wql : g_wqh) + (size_t)row * EMB + kb + c4 * 8;
                    dst = dstb + 2 * MATB_A + (uint32_t)mat * MATB_B
                              + (uint32_t)(row * PADB + c4 * 16);
                }
                CP16(dst, src);
            }
            CPCOMMIT();
        };

        load_stage(0, 0);
        const int nStages = 8;
        for (int s = 0; s < nStages; s++) {
            const int buf = s & 1;
            const bool more = (s + 1 < nStages);
            if (more) load_stage(s + 1, buf ^ 1);
            if (more) CPWAIT1(); else CPWAIT0();
            __syncthreads();

            const uint32_t bS = sbase + (uint32_t)buf * STGB;
            const uint32_t bAhi = bS, bAlo = bS + MATB_A;
            const uint32_t bBhi = bS + 2 * MATB_A, bBlo = bS + 2 * MATB_A + MATB_B;

            #pragma unroll
            for (int kk = 0; kk < 2; kk++) {
                const uint32_t kby = kk * 32;
                uint32_t ah[2][4], al[2][4];
                #pragma unroll
                for (int mi = 0; mi < 2; mi++) {
                    uint32_t adr = (uint32_t)((wm * 32 + mi * 16 + la) * PADB + ga * 16) + kby;
                    LDSM4(ah[mi][0], ah[mi][1], ah[mi][2], ah[mi][3], bAhi + adr);
                    LDSM4(al[mi][0], al[mi][1], al[mi][2], al[mi][3], bAlo + adr);
                }
                uint32_t bh[2][4], bl[2][4];
                #pragma unroll
                for (int nj = 0; nj < 2; nj++) {
                    uint32_t adr = (uint32_t)((wn * 32 + nj * 16 + lb + (gb >> 1) * 8) * PADB
                                              + (gb & 1) * 16) + kby;
                    LDSM4(bh[nj][0], bh[nj][1], bh[nj][2], bh[nj][3], bBhi + adr);
                    LDSM4(bl[nj][0], bl[nj][1], bl[nj][2], bl[nj][3], bBlo + adr);
                }
                #pragma unroll
                for (int mi = 0; mi < 2; mi++)
                    #pragma unroll
                    for (int t4 = 0; t4 < 4; t4++) {
                        const int nj = t4 >> 1, sel = (t4 & 1) * 2;
                        MMA16816(c[mi][t4], ah[mi], bh[nj][sel], bh[nj][sel + 1]);
                        MMA16816(c[mi][t4], al[mi], bh[nj][sel], bh[nj][sel + 1]);
                        MMA16816(c[mi][t4], ah[mi], bl[nj][sel], bl[nj][sel + 1]);
                    }
            }
            __syncthreads();
        }
    }

    // ---------- split q accums into smem ----------
    const int rit  = lane >> 2;
    const int colp = (lane & 3) * 2;
    #pragma unroll
    for (int mi = 0; mi < 2; mi++) {
        #pragma unroll
        for (int half = 0; half < 2; half++) {
            const int row = wm * 32 + mi * 16 + half * 8 + rit;
            #pragma unroll
            for (int t4 = 0; t4 < 4; t4++) {
                const int col = wn * 32 + t4 * 8 + colp;
                float v0 = c[mi][t4][half * 2 + 0];
                float v1 = c[mi][t4][half * 2 + 1];
                __nv_bfloat16 h0 = __float2bfloat16(v0);
                __nv_bfloat16 h1 = __float2bfloat16(v1);
                __nv_bfloat16 l0 = __float2bfloat16(v0 - __bfloat162float(h0));
                __nv_bfloat16 l1 = __float2bfloat16(v1 - __bfloat162float(h1));
                const uint32_t off = (uint32_t)(row * QSTRIDE + col * 2);
                *reinterpret_cast<__nv_bfloat162*>(dynsm + SQ_HI + off) = __nv_bfloat162(h0, h1);
                *reinterpret_cast<__nv_bfloat162*>(dynsm + SQ_LO + off) = __nv_bfloat162(l0, l1);
            }
        }
    }
    __syncthreads();

    // ---------- phase 2: qk[:, nt*128 .. ] = q @ WkT ----------
    const uint32_t sqhi = sbase + SQ_HI;
    const uint32_t sqlo = sbase + SQ_LO;
    const uint32_t sbhi = sbase + SB_OFF;
    const uint32_t sblo = sbase + SB_OFF + SB_MATB;

    for (int nt = 0; nt < 4; nt++) {
        const int h   = nt >> 1;
        const int sub = nt & 1;
        const size_t brow0 = (size_t)(h * EMB + sub * 128) * ADIM;

        // load WkT tile (128 d-rows x 64 a-cols, hi+lo): 2048 chunks, 8/thread
        #pragma unroll
        for (int i = 0; i < 8; i++) {
            int idx = i * 256 + t;
            int mat = idx >> 10;
            int rem = idx & 1023;
            int row = rem >> 3, c8 = rem & 7;
            const __nv_bfloat16* src = (mat ? g_wkl : g_wkh) + brow0 + (size_t)row * ADIM + c8 * 8;
            uint32_t dst = (mat ? sblo : sbhi) + (uint32_t)(row * SB_STR + c8 * 16);
            CP16(dst, src);
        }
        CPCOMMIT(); CPWAIT0();
        __syncthreads();

        #pragma unroll
        for (int mi = 0; mi < 2; mi++)
            #pragma unroll
            for (int t4 = 0; t4 < 4; t4++)
                #pragma unroll
                for (int r = 0; r < 4; r++) c[mi][t4][r] = 0.f;

        #pragma unroll
        for (int kk = 0; kk < 4; kk++) {
            const uint32_t kby = kk * 32;
            uint32_t ah[2][4], al[2][4];
            #pragma unroll
            for (int mi = 0; mi < 2; mi++) {
                uint32_t adr = (uint32_t)((wm * 32 + mi * 16 + la) * QSTRIDE + ga * 16 + h * 128) + kby;
                LDSM4(ah[mi][0], ah[mi][1], ah[mi][2], ah[mi][3], sqhi + adr);
                LDSM4(al[mi][0], al[mi][1], al[mi][2], al[mi][3], sqlo + adr);
            }
            uint32_t bh[2][4], bl[2][4];
            #pragma unroll
            for (int nj = 0; nj < 2; nj++) {
                uint32_t adr = (uint32_t)((wn * 32 + nj * 16 + lb + (gb >> 1) * 8) * SB_STR
                                          + (gb & 1) * 16) + kby;
                LDSM4(bh[nj][0], bh[nj][1], bh[nj][2], bh[nj][3], sbhi + adr);
                LDSM4(bl[nj][0], bl[nj][1], bl[nj][2], bl[nj][3], sblo + adr);
            }
            #pragma unroll
            for (int mi = 0; mi < 2; mi++)
                #pragma unroll
                for (int t4 = 0; t4 < 4; t4++) {
                    const int nj = t4 >> 1, sel = (t4 & 1) * 2;
                    MMA16816(c[mi][t4], ah[mi], bh[nj][sel], bh[nj][sel + 1]);
                    MMA16816(c[mi][t4], al[mi], bh[nj][sel], bh[nj][sel + 1]);
                    MMA16816(c[mi][t4], ah[mi], bl[nj][sel], bl[nj][sel + 1]);
                }
        }

        // epilogue: write qk fp32
        #pragma unroll
        for (int mi = 0; mi < 2; mi++) {
            #pragma unroll
            for (int half = 0; half < 2; half++) {
                const int gm = m0 + wm * 32 + mi * 16 + half * 8 + rit;
                #pragma unroll
                for (int t4 = 0; t4 < 4; t4++) {
                    const int col = nt * 128 + wn * 32 + t4 * 8 + colp;
                    *reinterpret_cast<float2*>(g_qk + (size_t)gm * 512 + col) =
                        make_float2(c[mi][t4][half * 2 + 0], c[mi][t4][half * 2 + 1]);
                }
            }
        }
        __syncthreads();
    }
}

// ---------------- out-GEMM: bf16x3 HMMA, BM=128, BN=128, BK=32, dbl-buffered ----------------
__global__ __launch_bounds__(256, 2) void gemm_mma(
    const __nv_bfloat16* __restrict__ Ahi, const __nv_bfloat16* __restrict__ Alo,
    int lda,
    const __nv_bfloat16* __restrict__ Bhi, const __nv_bfloat16* __restrict__ Blo,
    int ldb, int Kdim,
    float* __restrict__ Cf, int ldcf,
    const float* __restrict__ bias,
    const int* __restrict__ Cperm)
{
    extern __shared__ __align__(16) char dynsm[];

    const int nvalid = g_nvalid;
    const int m0 = blockIdx.y * 128;
    if (m0 >= nvalid) return;
    const int n0 = blockIdx.x * 128;

    const int t    = threadIdx.x;
    const int wid  = t >> 5;
    const int lane = t & 31;
    const int wm   = wid >> 1;          // 0..3
    const int wn   = wid & 1;           // 0..1

    const uint32_t sbase = smem_u32(dynsm);

    float c[2][8][4];
    #pragma unroll
    for (int mi = 0; mi < 2; mi++)
        #pragma unroll
        for (int nj = 0; nj < 8; nj++)
            #pragma unroll
            for (int r = 0; r < 4; r++) c[mi][nj][r] = 0.f;

    const int la = lane & 15, ga = lane >> 4;
    const int lb = lane & 7,  gb = lane >> 3;
    const uint32_t aoff = (uint32_t)((wm * 32 + la) * PADB + ga * 16);
    const uint32_t boff = (uint32_t)((wn * 64 + lb + (gb >> 1) * 8) * PADB + (gb & 1) * 16);

    const int nStages = Kdim >> 5;

    auto load_stage = [&](int s, int buf) {
        const int kb = s * 32;
        const uint32_t dstb = sbase + (uint32_t)buf * OG_STGB;
        #pragma unroll
        for (int i = 0; i < 8; i++) {
            int idx = i * 256 + t;
            int mat = idx >> 9;
            int rem = idx & 511;
            int row = rem >> 2, c4 = rem & 3;
            const __nv_bfloat16* src;
            if (mat == 0)      src = Ahi + (size_t)(m0 + row) * lda + kb + c4 * 8;
            else if (mat == 1) src = Alo + (size_t)(m0 + row) * lda + kb + c4 * 8;
            else if (mat == 2) src = Bhi + (size_t)(n0 + row) * ldb + kb + c4 * 8;
            else               src = Blo + (size_t)(n0 + row) * ldb + kb + c4 * 8;
            uint32_t dst = dstb + (uint32_t)mat * OG_MATB + (uint32_t)(row * PADB + c4 * 16);
            CP16(dst, src);
        }
        CPCOMMIT();
    };

    load_stage(0, 0);

    for (int s = 0; s < nStages; s++) {
        const int buf = s & 1;
        const bool more = (s + 1 < nStages);
        if (more) load_stage(s + 1, buf ^ 1);
        if (more) CPWAIT1(); else CPWAIT0();
        __syncthreads();

        const uint32_t bA = sbase + (uint32_t)buf * OG_STGB;
        const uint32_t bAhi = bA, bAlo = bA + OG_MATB;
        const uint32_t bBhi = bA + 2 * OG_MATB, bBlo = bA + 3 * OG_MATB;

        #pragma unroll
        for (int kk = 0; kk < 2; kk++) {
            const uint32_t kby = kk * 32;
            uint32_t ah[2][4], al[2][4];
            #pragma unroll
            for (int mi = 0; mi < 2; mi++) {
                uint32_t adr = aoff + (uint32_t)(mi * 16 * PADB) + kby;
                LDSM4(ah[mi][0], ah[mi][1], ah[mi][2], ah[mi][3], bAhi + adr);
                LDSM4(al[mi][0], al[mi][1], al[mi][2], al[mi][3], bAlo + adr);
            }
            uint32_t bh[4][4], bl[4][4];
            #pragma unroll
            for (int nj = 0; nj < 4; nj++) {
                uint32_t adr = boff + (uint32_t)(nj * 16 * PADB) + kby;
                LDSM4(bh[nj][0], bh[nj][1], bh[nj][2], bh[nj][3], bBhi + adr);
                LDSM4(bl[nj][0], bl[nj][1], bl[nj][2], bl[nj][3], bBlo + adr);
            }
            #pragma unroll
            for (int mi = 0; mi < 2; mi++)
                #pragma unroll
                for (int t8 = 0; t8 < 8; t8++) {
                    const int nj = t8 >> 1, sel = (t8 & 1) * 2;
                    MMA16816(c[mi][t8], ah[mi], bh[nj][sel], bh[nj][sel + 1]);
                    MMA16816(c[mi][t8], al[mi], bh[nj][sel], bh[nj][sel + 1]);
                    MMA16816(c[mi][t8], ah[mi], bl[nj][sel], bl[nj][sel + 1]);
                }
        }
        __syncthreads();
    }

    const int rit  = lane >> 2;
    const int colp = (lane & 3) * 2;
    #pragma unroll
    for (int mi = 0; mi < 2; mi++) {
        #pragma unroll
        for (int half = 0; half < 2; half++) {
            const int gm = m0 + wm * 32 + mi * 16 + half * 8 + rit;
            if (gm >= nvalid) continue;
            const int crow = Cperm ? Cperm[gm] : gm;
            #pragma unroll
            for (int t8 = 0; t8 < 8; t8++) {
                const int col = n0 + wn * 64 + t8 * 8 + colp;
                float v0 = c[mi][t8][half * 2 + 0];
                float v1 = c[mi][t8][half * 2 + 1];
                if (bias) { v0 += bias[col]; v1 += bias[col + 1]; }
                *reinterpret_cast<float2*>(Cf + (size_t)crow * ldcf + col) =
                    make_float2(v0, v1);
            }
        }
    }
}

// ---------------- fused attention (valid) + passthrough copy (invalid) ----------------
__global__ __launch_bounds__(128) void attn_kernel(
    const float* __restrict__ center,
    const float* __restrict__ neigh,
    const float* __restrict__ wts,
    const float* __restrict__ qk,
    float* __restrict__ out)
{
    const int i = blockIdx.x;
    const int t = threadIdx.x;
    const int b = g_perm[i];

    if (i >= g_nvalid) {
        const float4* src = reinterpret_cast<const float4*>(center + (long)b * EMB);
        float4*       dst = reinterpret_cast<float4*>(out + (long)b * EMB);
        if (t < 64) dst[t] = src[t];
        return;
    }

    __shared__ float sn[KNEI * EMB];
    __shared__ float sq[512];
    __shared__ float sscore[32];
    __shared__ float sattn[32];

    const float4* np = reinterpret_cast<const float4*>(neigh + (long)b * KNEI * EMB);
    float4* snp = reinterpret_cast<float4*>(sn);
    #pragma unroll
    for (int r = 0; r < 8; r++) snp[t + r * 128] = np[t + r * 128];
    reinterpret_cast<float4*>(sq)[t] =
        reinterpret_cast<const float4*>(qk + (long)i * 512)[t];
    __syncthreads();

    {
        const int g = t >> 2, sub = t & 3;
        const int h = g >> 4, j = g & 15;
        const float* qh = sq + h * EMB;
        const float* nj = sn + j * EMB;
        float p = 0.f;
        #pragma unroll 8
        for (int d = sub; d < EMB; d += 4) p += qh[d] * nj[d];
        p += __shfl_xor_sync(0xffffffffu, p, 1);
        p += __shfl_xor_sync(0xffffffffu, p, 2);
        if (sub == 0) sscore[g] = p * 0.125f;
    }
    __syncthreads();

    {
        const int wid = t >> 5, lane = t & 31;
        if (wid < NHEADS && lane < KNEI) {
            float s = sscore[wid * KNEI + lane];
            float m = s;
            #pragma unroll
            for (int o = 8; o > 0; o >>= 1) m = fmaxf(m, __shfl_xor_sync(0xffffu, m, o));
            float e = expf(s - m);
            float se = e;
            #pragma unroll
            for (int o = 8; o > 0; o >>= 1) se += __shfl_xor_sync(0xffffu, se, o);
            float a = (e / se) * wts[b * KNEI + lane];
            float sa = a;
            #pragma unroll
            for (int o = 8; o > 0; o >>= 1) sa += __shfl_xor_sync(0xffffu, sa, o);
            sattn[wid * KNEI + lane] = a / (sa + 1e-8f);
        }
    }
    __syncthreads();

    #pragma unroll
    for (int r = 0; r < 4; r++) {
        const int idx = r * 128 + t;
        const int d = idx & 255, h = idx >> 8;
        float acc = 0.f;
        #pragma unroll
        for (int j = 0; j < KNEI; j++) acc += sattn[h * KNEI + j] * sn[j * EMB + d];
        __nv_bfloat16 hi = __float2bfloat16(acc);
        g_cxh[(size_t)i * 512 + idx] = hi;
        g_cxl[(size_t)i * 512 + idx] = __float2bfloat16(acc - __bfloat162float(hi));
    }
}

// ---------------- launch ----------------
extern "C" void kernel_launch(void* const* d_in, const int* in_sizes, int n_in,
                              void* d_out, int out_size)
{
    const float* center = (const float*)d_in[0];
    const float* neigh  = (const float*)d_in[1];
    const float* wts    = (const float*)d_in[2];
    const void*  mask   = d_in[3];
    const float* Wq     = (const float*)d_in[4];   // [2, 64, 256]
    const float* Wk     = (const float*)d_in[5];   // [2, 64, 256]
    const float* Wout   = (const float*)d_in[6];   // [256, 512]
    const float* bout   = (const float*)d_in[7];
    float* out = (float*)d_out;

    __nv_bfloat16 *cxh, *cxl, *woh, *wol;
    float *gqk;
    int *gperm;
    cudaGetSymbolAddress((void**)&cxh, g_cxh); cudaGetSymbolAddress((void**)&cxl, g_cxl);
    cudaGetSymbolAddress((void**)&woh, g_woh); cudaGetSymbolAddress((void**)&wol, g_wol);
    cudaGetSymbolAddress((void**)&gqk, g_qk);
    cudaGetSymbolAddress((void**)&gperm, g_perm);

    cudaFuncSetAttribute(gemm_mma, cudaFuncAttributeMaxDynamicSharedMemorySize, OG_SMEM);
    cudaFuncSetAttribute(q_qk_fused, cudaFuncAttributeMaxDynamicSharedMemorySize, FUSED_SMEM);

    mask_compact<<<1, 1024>>>(mask);
    prep_weights<<<196608 / 256, 256>>>(Wq, Wk, Wout);
    gather_split_center<<<(BATCH * EMB) / 256, 256>>>(center);

    // fused q->qk: [Bv,512] in one kernel, q never leaves smem (BM=64)
    q_qk_fused<<<BATCH / 64, 256, FUSED_SMEM>>>();

    // attention on valid rows + passthrough on invalid rows
    attn_kernel<<<BATCH, 128>>>(center, neigh, wts, gqk, out);

    // out = ctx @ Wout^T + b : [Bv,256], K=512 -> fp32 scattered via perm (BM=128)
    {
        dim3 grid(2, BATCH / 128);
        gemm_mma<<<grid, 256, OG_SMEM>>>(cxh, cxl, 512, woh, wol, 512, 512,
                                         out, EMB, bout, gperm);
    }
}